// round 16
// baseline (speedup 1.0000x reference)
#include <cuda_runtime.h>
#include <cuda_fp16.h>

// Fixed problem: In (4,8,262144) f32, NNsites (13,262144) i32,
// Weights (8,8,16) f32, bias (8,8) f32. Output (4,8,262144) f32.
#define NSITES 262144

// Site-major features, fp16, PRE-SCALED by log2(e). Row = 32 half = 64 B.
// g_T[n][bo] = log2e *  sum_i Wn[o][i]*In[b][i][n]
// g_S[n][bo] = log2e * (sum_i Ws[o][i]*In[b][i][n] + beff[o])
__device__ __align__(256) __half2 g_T[NSITES * 16];
__device__ __align__(256) __half2 g_S[NSITES * 16];

__device__ __forceinline__ __half2 u32_as_h2(unsigned v) {
    return *reinterpret_cast<const __half2*>(&v);
}
__device__ __forceinline__ unsigned long long pack_f32x2(float lo, float hi) {
    unsigned long long r;
    asm("mov.b64 %0, {%1, %2};" : "=l"(r) : "f"(lo), "f"(hi));
    return r;
}
__device__ __forceinline__ void unpack_f32x2(unsigned long long v, float& lo, float& hi) {
    asm("mov.b64 {%0, %1}, %2;" : "=f"(lo), "=f"(hi) : "l"(v));
}
// acc = a*b + acc, packed fp32x2 (Blackwell FFMA2)
__device__ __forceinline__ void fma2_f32x2(unsigned long long& acc,
                                           unsigned long long a,
                                           unsigned long long b) {
    asm("fma.rn.f32x2 %0, %1, %2, %0;" : "+l"(acc) : "l"(a), "l"(b));
}
// acc (packed f32x2) += {a, b}
__device__ __forceinline__ void acc_f32x2(unsigned long long& acc, float a, float b) {
    unsigned long long t = pack_f32x2(a, b);
    asm("add.rn.f32x2 %0, %0, %1;" : "+l"(acc) : "l"(t));
}

// ---------------------------------------------------------------------------
// Pass 1: streaming T' + S' (fp16, log2e-scaled), site-major.
// 2 adjacent sites per thread (float2 In loads). Packed FFMA2: each
// accumulator holds {T,S} for one (site,o); weights in smem as {wn',ws'}
// u64 (one LDS.64 serves both sites). 128 FFMA2 replaces 256 FFMA —
// identical fp32 arithmetic order, bit-identical results.
// ---------------------------------------------------------------------------
__global__ __launch_bounds__(256) void pass1_kernel(
    const float* __restrict__ In,      // In[(b*8+i)*NSITES + n]
    const float* __restrict__ W,       // W[j*128 + o*16 + k]
    const float* __restrict__ bias)    // bias[j*8 + o]
{
    __shared__ unsigned long long sw2[8][8];   // {wn', ws'} per (o,i)
    __shared__ unsigned long long sbe2[8];     // {0, beff'}

    const int tid = threadIdx.x;
    const float L2E = 1.44269504f;

    if (tid < 64) {
        int o = tid >> 3, i = tid & 7;
        float wn = 0.f, ws = 0.f;
        #pragma unroll
        for (int j = 0; j < 8; j++) {
            ws += W[j * 128 + o * 16 + i];
            wn += W[j * 128 + o * 16 + 8 + i];
        }
        sw2[o][i] = pack_f32x2(wn * L2E, ws * L2E);
        if (i == 0) {
            float be = 0.f;
            #pragma unroll
            for (int j = 0; j < 8; j++) be += bias[j * 8 + o];
            sbe2[o] = pack_f32x2(0.f, be * L2E);
        }
    }
    __syncthreads();

    const int w   = tid >> 5, lane = tid & 31;
    const int sp  = w * 8 + (lane >> 2);     // site pair 0..63
    const int jj  = lane & 3;                // batch b
    const int n0  = blockIdx.x * 128 + sp * 2;

    float2 x[8];
    #pragma unroll
    for (int i = 0; i < 8; i++)
        x[i] = *(const float2*)&In[(jj * 8 + i) * NSITES + n0];

    // Duplicate each site's x across both fp32 lanes once.
    unsigned long long xd0[8], xd1[8];
    #pragma unroll
    for (int i = 0; i < 8; i++) {
        xd0[i] = pack_f32x2(x[i].x, x[i].x);
        xd1[i] = pack_f32x2(x[i].y, x[i].y);
    }

    float tv0[8], sv0[8], tv1[8], sv1[8];
    #pragma unroll
    for (int o = 0; o < 8; o++) {
        unsigned long long acc0 = sbe2[o];   // {t=0, s=beff'}
        unsigned long long acc1 = sbe2[o];
        #pragma unroll
        for (int i = 0; i < 8; i++) {
            unsigned long long wv = sw2[o][i];   // one LDS.64, two uses
            fma2_f32x2(acc0, wv, xd0[i]);        // {t+=wn*x0, s+=ws*x0}
            fma2_f32x2(acc1, wv, xd1[i]);
        }
        unpack_f32x2(acc0, tv0[o], sv0[o]);
        unpack_f32x2(acc1, tv1[o], sv1[o]);
    }

    #pragma unroll
    for (int s = 0; s < 2; s++) {
        const float* tv = s ? tv1 : tv0;
        const float* sv = s ? sv1 : sv0;
        __half2 th[4], sh[4];
        #pragma unroll
        for (int m = 0; m < 4; m++) {
            th[m] = __floats2half2_rn(tv[2 * m], tv[2 * m + 1]);
            sh[m] = __floats2half2_rn(sv[2 * m], sv[2 * m + 1]);
        }
        uint4 ut = make_uint4(*reinterpret_cast<unsigned*>(&th[0]),
                              *reinterpret_cast<unsigned*>(&th[1]),
                              *reinterpret_cast<unsigned*>(&th[2]),
                              *reinterpret_cast<unsigned*>(&th[3]));
        uint4 us = make_uint4(*reinterpret_cast<unsigned*>(&sh[0]),
                              *reinterpret_cast<unsigned*>(&sh[1]),
                              *reinterpret_cast<unsigned*>(&sh[2]),
                              *reinterpret_cast<unsigned*>(&sh[3]));
        ((uint4*)g_T)[(n0 + s) * 4 + jj] = ut;
        ((uint4*)g_S)[(n0 + s) * 4 + jj] = us;
    }
}

// ---------------------------------------------------------------------------
// Pass 2 (R15 exact, measured 33.9us): 6-wide gather batching at (256,5).
// out[bo][n] = sum_z softplus(S + T[nn]); log2e-scaled:
//   sum sp(x) = ln2 * ( sum max(x',0) + log2( prod (1+2^{-|x'|}) ) )
// NO smem, NO barriers. 4 lanes/site, 8 sites/warp, LDG.128 gathers.
// ---------------------------------------------------------------------------
__global__ __launch_bounds__(256, 5) void pass2_kernel(
    const int*   __restrict__ NN,      // NN[z*NSITES + n]
    float*       __restrict__ out)     // out[bo*NSITES + n]
{
    const int tid  = threadIdx.x;
    const int base = blockIdx.x * 64;
    const int w    = tid >> 5, lane = tid & 31;
    const int sl   = w * 8 + (lane >> 2);
    const int jj   = lane & 3;              // batch b; bo = jj*8..jj*8+7
    const int n    = base + sl;

    uint4 s4 = ((const uint4*)g_S)[n * 4 + jj];
    __half2 s2[4] = { u32_as_h2(s4.x), u32_as_h2(s4.y),
                      u32_as_h2(s4.z), u32_as_h2(s4.w) };

    int idx[12];
    #pragma unroll
    for (int z = 0; z < 12; z++) idx[z] = NN[(z + 1) * NSITES + n];

    const __half2 one2 = __float2half2_rn(1.f);
    const __half2 m22  = __float2half2_rn(-2.f);
    const uint4* __restrict__ Tp = (const uint4*)g_T;

    __half2 prod[4] = {one2, one2, one2, one2};
    unsigned long long lin[4] = {0ull, 0ull, 0ull, 0ull};

    #pragma unroll
    for (int zc = 0; zc < 2; zc++) {
        uint4 t4[6];
        #pragma unroll
        for (int z = 0; z < 6; z++)
            t4[z] = Tp[idx[zc * 6 + z] * 4 + jj];   // 6 x 64B gathers in flight
        unsigned tu[6][4] = {
            {t4[0].x, t4[0].y, t4[0].z, t4[0].w},
            {t4[1].x, t4[1].y, t4[1].z, t4[1].w},
            {t4[2].x, t4[2].y, t4[2].z, t4[2].w},
            {t4[3].x, t4[3].y, t4[3].z, t4[3].w},
            {t4[4].x, t4[4].y, t4[4].z, t4[4].w},
            {t4[5].x, t4[5].y, t4[5].z, t4[5].w}};
        #pragma unroll
        for (int m = 0; m < 4; m++) {
            __half2 r[6], nn2[6];
            #pragma unroll
            for (int z = 0; z < 6; z++) {
                __half2 t = u32_as_h2(tu[z][m]);
                r[z]   = __hfma2_relu(s2[m], one2, t);            // max(x',0)
                nn2[z] = __hadd2(__hfma2(r[z], m22, t), s2[m]);   // -|x'|
            }
            #pragma unroll
            for (int z = 0; z < 6; z++) {
                __half2 e = h2exp2(nn2[z]);
                prod[m] = __hfma2(prod[m], e, prod[m]);           // *= 1+2^n
            }
            __half2 rq = __hadd2(__hadd2(__hadd2(r[0], r[1]),
                                         __hadd2(r[2], r[3])),
                                 __hadd2(r[4], r[5]));            // 6-z tree
            float2 f = __half22float2(rq);
            acc_f32x2(lin[m], f.x, f.y);
        }
    }

    const float ln2 = 0.69314718f;
    #pragma unroll
    for (int m = 0; m < 4; m++) {
        float lx, ly;
        unpack_f32x2(lin[m], lx, ly);
        __half2 lg = h2log2(prod[m]);            // prod in (1,4096]: fp16-safe
        float2 g = __half22float2(lg);
        out[(jj * 8 + 2 * m + 0) * NSITES + n] = (lx + g.x) * ln2;
        out[(jj * 8 + 2 * m + 1) * NSITES + n] = (ly + g.y) * ln2;
    }
}

extern "C" void kernel_launch(void* const* d_in, const int* in_sizes, int n_in,
                              void* d_out, int out_size)
{
    const float* In   = (const float*)d_in[0];
    const int*   NN   = (const int*)  d_in[1];
    const float* W    = (const float*)d_in[2];
    const float* bias = (const float*)d_in[3];
    float*       out  = (float*)d_out;

    pass1_kernel<<<NSITES / 128, 256>>>(In, W, bias);
    pass2_kernel<<<NSITES / 64, 256>>>(NN, out);
}

// round 17
// speedup vs baseline: 1.0537x; 1.0537x over previous
#include <cuda_runtime.h>
#include <cuda_fp16.h>

// Fixed problem: In (4,8,262144) f32, NNsites (13,262144) i32,
// Weights (8,8,16) f32, bias (8,8) f32. Output (4,8,262144) f32.
#define NSITES 262144

// Site-major features, fp16, PRE-SCALED by log2(e). Row = 32 half = 64 B.
// g_T[n][bo] = log2e *  sum_i Wn[o][i]*In[b][i][n]
// g_S[n][bo] = log2e * (sum_i Ws[o][i]*In[b][i][n] + beff[o])
__device__ __align__(256) __half2 g_T[NSITES * 16];
__device__ __align__(256) __half2 g_S[NSITES * 16];

__device__ __forceinline__ __half2 u32_as_h2(unsigned v) {
    return *reinterpret_cast<const __half2*>(&v);
}
__device__ __forceinline__ unsigned h2_as_u32(__half2 v) {
    return *reinterpret_cast<unsigned*>(&v);
}
// acc (packed f32x2) += {a, b}
__device__ __forceinline__ void acc_f32x2(unsigned long long& acc, float a, float b) {
    unsigned long long t;
    asm("mov.b64 %0, {%1, %2};" : "=l"(t) : "f"(a), "f"(b));
    asm("add.rn.f32x2 %0, %0, %1;" : "+l"(acc) : "l"(t));
}
__device__ __forceinline__ void unpack_f32x2(unsigned long long v, float& lo, float& hi) {
    asm("mov.b64 {%0, %1}, %2;" : "=f"(lo), "=f"(hi) : "l"(v));
}

// ---------------------------------------------------------------------------
// Pass 1 (R14 exact, best measured 15.5us): streaming T' + S', site-major.
// 2 adjacent sites per thread via float2 In loads, 128 sites/CTA.
// ---------------------------------------------------------------------------
__global__ __launch_bounds__(256) void pass1_kernel(
    const float* __restrict__ In,      // In[(b*8+i)*NSITES + n]
    const float* __restrict__ W,       // W[j*128 + o*16 + k]
    const float* __restrict__ bias)    // bias[j*8 + o]
{
    __shared__ float2 sw[8][8];        // {wn', ws'} per (o,i)
    __shared__ float  sbe[8];

    const int tid = threadIdx.x;
    const float L2E = 1.44269504f;

    if (tid < 64) {
        int o = tid >> 3, i = tid & 7;
        float wn = 0.f, ws = 0.f;
        #pragma unroll
        for (int j = 0; j < 8; j++) {
            ws += W[j * 128 + o * 16 + i];
            wn += W[j * 128 + o * 16 + 8 + i];
        }
        sw[o][i] = make_float2(wn * L2E, ws * L2E);
        if (i == 0) {
            float be = 0.f;
            #pragma unroll
            for (int j = 0; j < 8; j++) be += bias[j * 8 + o];
            sbe[o] = be * L2E;
        }
    }
    __syncthreads();

    const int w   = tid >> 5, lane = tid & 31;
    const int sp  = w * 8 + (lane >> 2);     // site pair 0..63
    const int jj  = lane & 3;                // batch b
    const int n0  = blockIdx.x * 128 + sp * 2;

    float2 x[8];
    #pragma unroll
    for (int i = 0; i < 8; i++)
        x[i] = *(const float2*)&In[(jj * 8 + i) * NSITES + n0];

    float tv0[8], sv0[8], tv1[8], sv1[8];
    #pragma unroll
    for (int o = 0; o < 8; o++) {
        float at0 = 0.f, at1 = 0.f, as0 = sbe[o], as1 = as0;
        #pragma unroll
        for (int i = 0; i < 8; i++) {
            float2 wv = sw[o][i];           // LDS.64 broadcast
            at0 = fmaf(wv.x, x[i].x, at0);
            as0 = fmaf(wv.y, x[i].x, as0);
            at1 = fmaf(wv.x, x[i].y, at1);
            as1 = fmaf(wv.y, x[i].y, as1);
        }
        tv0[o] = at0; sv0[o] = as0;
        tv1[o] = at1; sv1[o] = as1;
    }

    #pragma unroll
    for (int s = 0; s < 2; s++) {
        const float* tv = s ? tv1 : tv0;
        const float* sv = s ? sv1 : sv0;
        __half2 th[4], sh[4];
        #pragma unroll
        for (int m = 0; m < 4; m++) {
            th[m] = __floats2half2_rn(tv[2 * m], tv[2 * m + 1]);
            sh[m] = __floats2half2_rn(sv[2 * m], sv[2 * m + 1]);
        }
        uint4 ut = make_uint4(h2_as_u32(th[0]), h2_as_u32(th[1]),
                              h2_as_u32(th[2]), h2_as_u32(th[3]));
        uint4 us = make_uint4(h2_as_u32(sh[0]), h2_as_u32(sh[1]),
                              h2_as_u32(sh[2]), h2_as_u32(sh[3]));
        ((uint4*)g_T)[(n0 + s) * 4 + jj] = ut;
        ((uint4*)g_S)[(n0 + s) * 4 + jj] = us;
    }
}

// ---------------------------------------------------------------------------
// Pass 2: 6-wide gather batching at (256,5); inner math retuned to offload
// the fma pipe:
//   x' = hadd2(s, t)              [fma]
//   r  = hmax2(x', 0)             [fma]   = max(x',0)
//   mu = x' | 0x80008000          [alu]   = -|x'|   (force sign bit)
//   e  = ex2.f16x2(mu)            [mufu]
//   prod = hfma2(prod, e, prod)   [fma]
// 4 fma ops per (z,m) instead of 5; alu pipe (13% busy) absorbs the OR.
// out[bo][n] = ln2 * ( sum max(x',0) + log2( prod (1+2^{-|x'|}) ) )
// ---------------------------------------------------------------------------
__global__ __launch_bounds__(256, 5) void pass2_kernel(
    const int*   __restrict__ NN,      // NN[z*NSITES + n]
    float*       __restrict__ out)     // out[bo*NSITES + n]
{
    const int tid  = threadIdx.x;
    const int base = blockIdx.x * 64;
    const int w    = tid >> 5, lane = tid & 31;
    const int sl   = w * 8 + (lane >> 2);
    const int jj   = lane & 3;              // batch b; bo = jj*8..jj*8+7
    const int n    = base + sl;

    uint4 s4 = ((const uint4*)g_S)[n * 4 + jj];
    __half2 s2[4] = { u32_as_h2(s4.x), u32_as_h2(s4.y),
                      u32_as_h2(s4.z), u32_as_h2(s4.w) };

    int idx[12];
    #pragma unroll
    for (int z = 0; z < 12; z++) idx[z] = NN[(z + 1) * NSITES + n];

    const __half2 zero2 = __float2half2_rn(0.f);
    const __half2 one2  = __float2half2_rn(1.f);
    const uint4* __restrict__ Tp = (const uint4*)g_T;

    __half2 prod[4] = {one2, one2, one2, one2};
    unsigned long long lin[4] = {0ull, 0ull, 0ull, 0ull};

    #pragma unroll
    for (int zc = 0; zc < 2; zc++) {
        uint4 t4[6];
        #pragma unroll
        for (int z = 0; z < 6; z++)
            t4[z] = Tp[idx[zc * 6 + z] * 4 + jj];   // 6 x 64B gathers in flight
        unsigned tu[6][4] = {
            {t4[0].x, t4[0].y, t4[0].z, t4[0].w},
            {t4[1].x, t4[1].y, t4[1].z, t4[1].w},
            {t4[2].x, t4[2].y, t4[2].z, t4[2].w},
            {t4[3].x, t4[3].y, t4[3].z, t4[3].w},
            {t4[4].x, t4[4].y, t4[4].z, t4[4].w},
            {t4[5].x, t4[5].y, t4[5].z, t4[5].w}};
        #pragma unroll
        for (int m = 0; m < 4; m++) {
            __half2 r[6], mu[6];
            #pragma unroll
            for (int z = 0; z < 6; z++) {
                __half2 xp = __hadd2(s2[m], u32_as_h2(tu[z][m]));   // x'
                r[z] = __hmax2(xp, zero2);                          // max(x',0)
                mu[z] = u32_as_h2(h2_as_u32(xp) | 0x80008000u);     // -|x'| (alu)
            }
            #pragma unroll
            for (int z = 0; z < 6; z++) {
                __half2 e = h2exp2(mu[z]);
                prod[m] = __hfma2(prod[m], e, prod[m]);             // *= 1+2^mu
            }
            __half2 rq = __hadd2(__hadd2(__hadd2(r[0], r[1]),
                                         __hadd2(r[2], r[3])),
                                 __hadd2(r[4], r[5]));              // 6-z tree
            float2 f = __half22float2(rq);
            acc_f32x2(lin[m], f.x, f.y);
        }
    }

    const float ln2 = 0.69314718f;
    #pragma unroll
    for (int m = 0; m < 4; m++) {
        float lx, ly;
        unpack_f32x2(lin[m], lx, ly);
        __half2 lg = h2log2(prod[m]);            // prod in (1,4096]: fp16-safe
        float2 g = __half22float2(lg);
        out[(jj * 8 + 2 * m + 0) * NSITES + n] = (lx + g.x) * ln2;
        out[(jj * 8 + 2 * m + 1) * NSITES + n] = (ly + g.y) * ln2;
    }
}

extern "C" void kernel_launch(void* const* d_in, const int* in_sizes, int n_in,
                              void* d_out, int out_size)
{
    const float* In   = (const float*)d_in[0];
    const int*   NN   = (const int*)  d_in[1];
    const float* W    = (const float*)d_in[2];
    const float* bias = (const float*)d_in[3];
    float*       out  = (float*)d_out;

    pass1_kernel<<<NSITES / 128, 256>>>(In, W, bias);
    pass2_kernel<<<NSITES / 64, 256>>>(NN, out);
}